// round 5
// baseline (speedup 1.0000x reference)
#include <cuda_runtime.h>
#include <math.h>

typedef unsigned long long u64;
typedef ulonglong2 u64x2;

#define F_TOL_F 1e-6f
#define NBLK 128
#define NSLAB 384u  // 64 (phase A, W2T) + 20*16 (iters, WzT)
#define SOLVER_SMEM 222752

// ---------------- device-global scratch (no allocations allowed) ------------
__device__ float g_h1[1024 * 1024];
__device__ float g_h2[1024 * 1024];
__device__ float g_W2T[1024 * 256];
__device__ float g_WzT[256 * 256];
__device__ float g_AT[256 * 128];
__device__ float g_biasproj[256];
__device__ unsigned g_res_arr[20];
__device__ unsigned g_solver_done;

// ---------------- packed fp32x2 (Blackwell double-rate fp32) ----------------
#define FFMA2(acc, a, b) \
    asm("fma.rn.f32x2 %0, %1, %2, %0;" : "+l"(acc) : "l"(a), "l"(b))
#define ADD2(acc, a) \
    asm("add.rn.f32x2 %0, %1, %0;" : "+l"(acc) : "l"(a))

__device__ __forceinline__ float2 unpack2(u64 v) {
    float2 p;
    asm("mov.b64 {%0,%1}, %2;" : "=f"(p.x), "=f"(p.y) : "l"(v));
    return p;
}

#define CP_COMMIT asm volatile("cp.async.commit_group;" ::: "memory")
#define CP_WAIT1 asm volatile("cp.async.wait_group 1;" ::: "memory")

__device__ __forceinline__ void cp16(unsigned dst, const void* src) {
    asm volatile("cp.async.cg.shared.global [%0], [%1], 16;" ::"r"(dst),
                 "l"(src));
}

// ---------------- fused prep: 3 transposes + biasproj + state reset ---------
__global__ void prep_kernel(const float* __restrict__ W2,
                            const float* __restrict__ Wz,
                            const float* __restrict__ Am,
                            const float* __restrict__ bvec,
                            const float* __restrict__ WbP) {
    __shared__ float tb[32][33];
    const int b = blockIdx.x;
    const int t = threadIdx.x;
    const int tx = t & 31, ty = t >> 5;

    const float* in;
    float* out;
    int R, C, bx, by;
    if (b < 256) {
        in = W2; out = g_W2T; R = 256; C = 1024; bx = b & 31; by = b >> 5;
    } else if (b < 320) {
        int bb = b - 256;
        in = Wz; out = g_WzT; R = 256; C = 256; bx = bb & 7; by = bb >> 3;
    } else if (b < 352) {
        int bb = b - 320;
        in = Am; out = g_AT; R = 128; C = 256; bx = bb & 7; by = bb >> 3;
    } else {
        if (t < 20) g_res_arr[t] = 0u;
        if (t == 32) g_solver_done = 0u;
        if (t >= 256 && t < 512) {
            int j = t - 256;
            float s = 0.f;
#pragma unroll 8
            for (int i = 0; i < 128; i++) s += bvec[i] * WbP[j * 128 + i];
            g_biasproj[j] = s;
        }
        return;
    }
    int c = bx * 32 + tx, r = by * 32 + ty;
    tb[ty][tx] = in[r * C + c];
    __syncthreads();
    int oc = by * 32 + tx;
    int orr = bx * 32 + ty;
    out[orr * R + oc] = tb[tx][ty];
}

// ---------------- FFMA2 SGEMM: C = relu(A @ B^T + bias) ----------------------
__global__ __launch_bounds__(256, 2) void gemm_relu_f2(
    const float* __restrict__ A, const float* __restrict__ B,
    const float* __restrict__ bias, float* __restrict__ C,
    int M, int N, int K) {
    __shared__ __align__(16) float2 As2[2][8][128];
    __shared__ __align__(16) float Bs[2][8][64];

    const int tid = threadIdx.x;
    const int tx = tid & 15, ty = tid >> 4;
    const int rowBase = blockIdx.y * 128;
    const int colBase = blockIdx.x * 64;

    const int arow = tid >> 1, aseg = tid & 1;
    const int brow = tid >> 2, bseg = tid & 3;

    const float* Aload = A + (rowBase + arow) * K + aseg * 4;
    const float* Bload = B + (colBase + brow) * K + bseg * 2;

    u64 acc[8][2];
#pragma unroll
    for (int i = 0; i < 8; i++)
#pragma unroll
        for (int j = 0; j < 2; j++) acc[i][j] = 0ull;

    {
        float4 av = *(const float4*)(Aload);
        float2 bv = *(const float2*)(Bload);
        As2[0][aseg * 4 + 0][arow] = make_float2(av.x, av.x);
        As2[0][aseg * 4 + 1][arow] = make_float2(av.y, av.y);
        As2[0][aseg * 4 + 2][arow] = make_float2(av.z, av.z);
        As2[0][aseg * 4 + 3][arow] = make_float2(av.w, av.w);
        Bs[0][bseg * 2 + 0][brow] = bv.x;
        Bs[0][bseg * 2 + 1][brow] = bv.y;
    }
    __syncthreads();

    const int nch = K >> 3;
    for (int ch = 0; ch < nch; ch++) {
        const int buf = ch & 1;
        float4 av;
        float2 bv;
        if (ch + 1 < nch) {
            av = *(const float4*)(Aload + (ch + 1) * 8);
            bv = *(const float2*)(Bload + (ch + 1) * 8);
        }
#pragma unroll
        for (int k = 0; k < 8; k++) {
            u64x2 a[4];
#pragma unroll
            for (int p = 0; p < 4; p++)
                a[p] = *(const u64x2*)&As2[buf][k][ty * 8 + 2 * p];
            u64x2 bb = *(const u64x2*)&Bs[buf][k][tx * 4];
#pragma unroll
            for (int p = 0; p < 4; p++) {
                FFMA2(acc[2 * p][0], a[p].x, bb.x);
                FFMA2(acc[2 * p][1], a[p].x, bb.y);
                FFMA2(acc[2 * p + 1][0], a[p].y, bb.x);
                FFMA2(acc[2 * p + 1][1], a[p].y, bb.y);
            }
        }
        if (ch + 1 < nch) {
            const int nb = buf ^ 1;
            As2[nb][aseg * 4 + 0][arow] = make_float2(av.x, av.x);
            As2[nb][aseg * 4 + 1][arow] = make_float2(av.y, av.y);
            As2[nb][aseg * 4 + 2][arow] = make_float2(av.z, av.z);
            As2[nb][aseg * 4 + 3][arow] = make_float2(av.w, av.w);
            Bs[nb][bseg * 2 + 0][brow] = bv.x;
            Bs[nb][bseg * 2 + 1][brow] = bv.y;
        }
        __syncthreads();
    }

#pragma unroll
    for (int i = 0; i < 8; i++) {
        const int m = rowBase + ty * 8 + i;
        const int n = colBase + 4 * tx;
        float2 v0 = unpack2(acc[i][0]);
        float2 v1 = unpack2(acc[i][1]);
        float4 o;
        o.x = fmaxf(v0.x + bias[n + 0], 0.f);
        o.y = fmaxf(v0.y + bias[n + 1], 0.f);
        o.z = fmaxf(v1.x + bias[n + 2], 0.f);
        o.w = fmaxf(v1.y + bias[n + 3], 0.f);
        *(float4*)&C[m * N + n] = o;
    }
}

// ---------------- solver helpers ---------------------------------------------
// MAC over one 16-k slab: 2 rows (2rg, 2rg+1) x 4 cols (c0..c0+3), full slab.
__device__ __forceinline__ void slab_mac(u64 acc[2][2], const float* wbuf,
                                         const float2 (*zsrc)[10], int kbase,
                                         int rg2, int c0) {
#pragma unroll
    for (int kk = 0; kk < 16; kk++) {
        u64x2 w = *(const u64x2*)(wbuf + kk * 256 + c0);
        u64x2 z = *(const u64x2*)&zsrc[kbase + kk][rg2];
        FFMA2(acc[0][0], z.x, w.x);
        FFMA2(acc[0][1], z.x, w.y);
        FFMA2(acc[1][0], z.y, w.x);
        FFMA2(acc[1][1], z.y, w.y);
    }
}

// ---------------- persistent solver: cp.async-pipelined, combine-free --------
// 128 blocks x 256 threads; block b owns rows [8b, 8b+8).
// Thread: cg = t&63 -> cols c0=4cg; rg = t>>6 -> rows 2rg, 2rg+1; full K.
__global__ __launch_bounds__(256) void solver_kernel(const float* __restrict__ b2,
                                                     const float* __restrict__ bvec,
                                                     float* __restrict__ outp) {
    extern __shared__ __align__(16) char sm[];
    float2(*zdup)[10] = (float2(*)[10])sm;             // 20480  @ 0
    float2(*hdup)[10] = (float2(*)[10])(sm + 20480);   // 20480  @ 20480
    float* Asm = (float*)(sm + 40960);                 // 131072 @ 40960
    float* wsl = (float*)(sm + 172032);                // 49152  @ 172032 (3 slabs)
    float* bvs = (float*)(sm + 221184);                // 512
    u64* bps = (u64*)(sm + 221696);                    // 1024
    float* redbuf = (float*)(sm + 222720);             // 32

    const int t = threadIdx.x;
    const int r0 = blockIdx.x * 8;
    const int cg = t & 63;
    const int c0 = cg * 4;
    const int rg2 = (t >> 6) * 2;  // rows rg2, rg2+1
    float* const zoutp = outp;
    float* const out0p = outp + 1024 * 256;

    const unsigned wslu = (unsigned)__cvta_generic_to_shared(wsl);

    // prologue: prefetch slabs 0 and 1 (phase A W2T stream)
    unsigned gpre = 0;
#pragma unroll
    for (int pp = 0; pp < 2; pp++) {
        const float* src = g_W2T + gpre * 4096u + t * 4u;
        unsigned dst = wslu + (gpre % 3u) * 16384u + t * 16u;
#pragma unroll
        for (int j = 0; j < 4; j++) cp16(dst + j * 4096u, src + j * 1024u);
        CP_COMMIT;
        gpre++;
    }

    if (t < 128) {
        bvs[t] = bvec[t];
        bps[t] = *(const u64*)&g_biasproj[2 * t];
    }
    // stage AT into smem
    {
        const float4* src = (const float4*)g_AT;
        float4* dst = (float4*)Asm;
#pragma unroll
        for (int i = t; i < 8192; i += 256) dst[i] = src[i];
    }

    unsigned gcons = 0;

    // ---- phase A: out = h2 rows @ W2T + b2 ----
    u64 accA[2][2] = {{0ull, 0ull}, {0ull, 0ull}};
    for (int c = 0; c < 4; c++) {
        __syncthreads();
#pragma unroll
        for (int jj = 0; jj < 8; jj++) {
            int idx = t + 256 * jj;
            int k = idx & 255, r = idx >> 8;
            float v = g_h2[(r0 + r) * 1024 + c * 256 + k];
            hdup[k][r] = make_float2(v, v);
        }
        for (int ls = 0; ls < 16; ls++) {
            CP_WAIT1;
            __syncthreads();
            if (gpre < NSLAB) {
                const float* base = (gpre < 64u)
                                        ? (g_W2T + gpre * 4096u)
                                        : (g_WzT + ((gpre - 64u) & 15u) * 4096u);
                const float* src = base + t * 4u;
                unsigned dst = wslu + (gpre % 3u) * 16384u + t * 16u;
#pragma unroll
                for (int j = 0; j < 4; j++) cp16(dst + j * 4096u, src + j * 1024u);
            }
            gpre++;
            CP_COMMIT;
            slab_mac(accA, wsl + (gcons % 3u) * 4096u, hdup, ls * 16, rg2, c0);
            gcons++;
        }
    }
    __syncthreads();
    {
        u64 bA = *(const u64*)&b2[c0];
        u64 bB = *(const u64*)&b2[c0 + 2];
        ADD2(accA[0][0], bA);
        ADD2(accA[0][1], bB);
        ADD2(accA[1][0], bA);
        ADD2(accA[1][1], bB);
#pragma unroll
        for (int i = 0; i < 2; i++) {
            float2 v0 = unpack2(accA[i][0]);
            float2 v1 = unpack2(accA[i][1]);
            float4 o = make_float4(v0.x, v0.y, v1.x, v1.y);
            *(float4*)&out0p[(r0 + rg2 + i) * 256 + c0] = o;
            zdup[c0 + 0][rg2 + i] = make_float2(o.x, o.x);
            zdup[c0 + 1][rg2 + i] = make_float2(o.y, o.y);
            zdup[c0 + 2][rg2 + i] = make_float2(o.z, o.z);
            zdup[c0 + 3][rg2 + i] = make_float2(o.w, o.w);
        }
    }
    __syncthreads();

    // ---- 20 fixed iterations ----
    const u64 bpA = bps ? 0ull : 0ull;  // (placeholder; real init below)
    const int ag = t & 31;
    const int ac0 = ag * 4;
    const int rrow = t >> 5;  // residual row 0..7

    for (int it = 0; it < 20; it++) {
        // z-update: acc = bias_proj + z @ WzT (full k, 16 slabs)
        u64 acc[2][2];
        {
            u64 bA = bps[2 * cg];
            u64 bB = bps[2 * cg + 1];
            acc[0][0] = bA;
            acc[0][1] = bB;
            acc[1][0] = bA;
            acc[1][1] = bB;
        }
        for (int s = 0; s < 16; s++) {
            CP_WAIT1;
            __syncthreads();
            if (gpre < NSLAB) {
                const float* src = g_WzT + ((gpre - 64u) & 15u) * 4096u + t * 4u;
                unsigned dst = wslu + (gpre % 3u) * 16384u + t * 16u;
#pragma unroll
                for (int j = 0; j < 4; j++) cp16(dst + j * 4096u, src + j * 1024u);
            }
            gpre++;
            CP_COMMIT;
            slab_mac(acc, wsl + (gcons % 3u) * 4096u, zdup, s * 16, rg2, c0);
            gcons++;
        }
        __syncthreads();
        // projection + write new z (duplicated layout)
#pragma unroll
        for (int i = 0; i < 2; i++) {
            float2 v0 = unpack2(acc[i][0]);
            float2 v1 = unpack2(acc[i][1]);
            if (cg >= 16) {  // cols >= 64 -> relu
                v0.x = fmaxf(v0.x, 0.f);
                v0.y = fmaxf(v0.y, 0.f);
                v1.x = fmaxf(v1.x, 0.f);
                v1.y = fmaxf(v1.y, 0.f);
            }
            zdup[c0 + 0][rg2 + i] = make_float2(v0.x, v0.x);
            zdup[c0 + 1][rg2 + i] = make_float2(v0.y, v0.y);
            zdup[c0 + 2][rg2 + i] = make_float2(v1.x, v1.x);
            zdup[c0 + 3][rg2 + i] = make_float2(v1.y, v1.y);
        }
        __syncthreads();

        // residual: row rrow, cols ac0..ac0+3, full k from smem
        u64 rac0 = 0ull, rac1 = 0ull;
#pragma unroll 8
        for (int k = 0; k < 256; k++) {
            u64x2 a2 = *(const u64x2*)&Asm[k * 128 + ac0];
            u64 z = *(const u64*)&zdup[k][rrow];
            FFMA2(rac0, z, a2.x);
            FFMA2(rac1, z, a2.y);
        }
        float m;
        {
            float2 v0 = unpack2(rac0);
            float2 v1 = unpack2(rac1);
            m = fmaxf(fmaxf(fabsf(v0.x - bvs[ac0]), fabsf(v0.y - bvs[ac0 + 1])),
                      fmaxf(fabsf(v1.x - bvs[ac0 + 2]),
                            fabsf(v1.y - bvs[ac0 + 3])));
        }
#pragma unroll
        for (int o = 16; o; o >>= 1) m = fmaxf(m, __shfl_xor_sync(~0u, m, o));
        if ((t & 31) == 0) redbuf[t >> 5] = m;
        __syncthreads();
        if (t == 0) {
            float bm = redbuf[0];
#pragma unroll
            for (int w = 1; w < 8; w++) bm = fmaxf(bm, redbuf[w]);
            atomicMax(&g_res_arr[it], __float_as_uint(bm));
        }
    }
    __syncthreads();

    // write z_star directly to d_out
#pragma unroll
    for (int jj = 0; jj < 8; jj++) {
        int idx = t + 256 * jj;
        int c = idx & 255, r = idx >> 8;
        zoutp[(r0 + r) * 256 + c] = zdup[c][r].x;
    }
    __syncthreads();
    __threadfence();
    if (t == 0) {
        if (atomicAdd(&g_solver_done, 1u) == NBLK - 1) {
            int it = 21;
            for (int tt = 0; tt < 20; tt++) {
                if (__uint_as_float(g_res_arr[tt]) <= F_TOL_F) {
                    it = tt + 2;
                    break;
                }
            }
            outp[2 * 1024 * 256] = (float)it;
        }
    }
}

// ---------------- launch ------------------------------------------------------
extern "C" void kernel_launch(void* const* d_in, const int* in_sizes, int n_in,
                              void* d_out, int out_size) {
    const float* b_primal = (const float*)d_in[0];
    const float* W0 = (const float*)d_in[1];
    const float* b0 = (const float*)d_in[2];
    const float* W1 = (const float*)d_in[3];
    const float* b1 = (const float*)d_in[4];
    const float* W2 = (const float*)d_in[5];
    const float* b2 = (const float*)d_in[6];
    const float* Amat = (const float*)d_in[7];
    const float* b_vec = (const float*)d_in[8];
    const float* WzProj = (const float*)d_in[9];
    const float* WbProj = (const float*)d_in[10];

    float *h1, *h2;
    cudaGetSymbolAddress((void**)&h1, g_h1);
    cudaGetSymbolAddress((void**)&h2, g_h2);

    static int smem_set = 0;
    if (!smem_set) {
        cudaFuncSetAttribute(solver_kernel,
                             cudaFuncAttributeMaxDynamicSharedMemorySize,
                             SOLVER_SMEM);
        smem_set = 1;
    }

    prep_kernel<<<353, 1024>>>(W2, WzProj, Amat, b_vec, WbProj);

    gemm_relu_f2<<<dim3(16, 8), 256>>>(b_primal, W0, b0, h1, 1024, 1024, 512);
    gemm_relu_f2<<<dim3(16, 8), 256>>>(h1, W1, b1, h2, 1024, 1024, 1024);

    solver_kernel<<<NBLK, 256, SOLVER_SMEM>>>(b2, b_vec, (float*)d_out);
}

// round 6
// speedup vs baseline: 1.4966x; 1.4966x over previous
#include <cuda_runtime.h>
#include <math.h>

typedef unsigned long long u64;
typedef ulonglong2 u64x2;

#define F_TOL_F 1e-6f
#define NBLK 128
#define SOLVER_SMEM 208448

// ---------------- device-global scratch (no allocations allowed) ------------
__device__ float g_h1[1024 * 1024];
__device__ float g_h2[1024 * 1024];
__device__ float g_W2T[1024 * 256];
__device__ float g_WzT[256 * 256];
__device__ float g_AT[256 * 128];
__device__ float g_biasproj[256];
__device__ unsigned g_res_arr[20];
__device__ unsigned g_solver_done;

// ---------------- packed fp32x2 (Blackwell double-rate fp32) ----------------
#define FFMA2(acc, a, b) \
    asm("fma.rn.f32x2 %0, %1, %2, %0;" : "+l"(acc) : "l"(a), "l"(b))
#define ADD2(acc, a) \
    asm("add.rn.f32x2 %0, %1, %0;" : "+l"(acc) : "l"(a))

__device__ __forceinline__ float2 unpack2(u64 v) {
    float2 p;
    asm("mov.b64 {%0,%1}, %2;" : "=f"(p.x), "=f"(p.y) : "l"(v));
    return p;
}
__device__ __forceinline__ u64 pack2(float lo, float hi) {
    u64 r;
    asm("mov.b64 %0, {%1,%2};" : "=l"(r) : "f"(lo), "f"(hi));
    return r;
}
// swap halves of a packed pair (2 MOVs on alu pipe)
__device__ __forceinline__ u64 swp(u64 v) {
    float2 f = unpack2(v);
    return pack2(f.y, f.x);
}

// ---------------- fused prep: 3 transposes + biasproj + state reset ---------
__global__ void prep_kernel(const float* __restrict__ W2,
                            const float* __restrict__ Wz,
                            const float* __restrict__ Am,
                            const float* __restrict__ bvec,
                            const float* __restrict__ WbP) {
    __shared__ float tb[32][33];
    const int b = blockIdx.x;
    const int t = threadIdx.x;
    const int tx = t & 31, ty = t >> 5;

    const float* in;
    float* out;
    int R, C, bx, by;
    if (b < 256) {
        in = W2; out = g_W2T; R = 256; C = 1024; bx = b & 31; by = b >> 5;
    } else if (b < 320) {
        int bb = b - 256;
        in = Wz; out = g_WzT; R = 256; C = 256; bx = bb & 7; by = bb >> 3;
    } else if (b < 352) {
        int bb = b - 320;
        in = Am; out = g_AT; R = 128; C = 256; bx = bb & 7; by = bb >> 3;
    } else {
        if (t < 20) g_res_arr[t] = 0u;
        if (t == 32) g_solver_done = 0u;
        if (t >= 256 && t < 512) {
            int j = t - 256;
            float s = 0.f;
#pragma unroll 8
            for (int i = 0; i < 128; i++) s += bvec[i] * WbP[j * 128 + i];
            g_biasproj[j] = s;
        }
        return;
    }
    int c = bx * 32 + tx, r = by * 32 + ty;
    tb[ty][tx] = in[r * C + c];
    __syncthreads();
    int oc = by * 32 + tx;
    int orr = bx * 32 + ty;
    out[orr * R + oc] = tb[tx][ty];
}

// ---------------- FFMA2 SGEMM: C = relu(A @ B^T + bias) ----------------------
// BM=128, BN=64, BK=16 double-buffered, 256 threads.
// Thread tile 8 rows x 4 cols, row-pair packed accumulators + w-swap trick.
// Per k: 2 LDS.128 (A, 8 rows natural) + 1 LDS.128 (B, 4 cols) -> 16 FFMA2.
__global__ __launch_bounds__(256, 2) void gemm_relu_f2(
    const float* __restrict__ A, const float* __restrict__ B,
    const float* __restrict__ bias, float* __restrict__ C,
    int M, int N, int K) {
    __shared__ __align__(16) float As[2][16][128];
    __shared__ __align__(16) float Bs[2][16][64];

    const int t = threadIdx.x;
    const int tx = t & 15, ty = t >> 4;
    const int rowBase = blockIdx.y * 128;
    const int colBase = blockIdx.x * 64;
    const int c0 = 4 * tx, r0 = 8 * ty;

    const int rA = t >> 2, kseg = (t & 3) * 4;

    const float* Aload = A + (rowBase + rA) * K + kseg;
    const float* Aload2 = A + (rowBase + rA + 64) * K + kseg;
    const float* Bload = B + (colBase + rA) * K + kseg;

    u64 ad[4][2], ax[4][2];
#pragma unroll
    for (int rp = 0; rp < 4; rp++)
#pragma unroll
        for (int cp = 0; cp < 2; cp++) ad[rp][cp] = ax[rp][cp] = 0ull;

    // stage tile 0
    {
        float4 a1 = *(const float4*)(Aload);
        float4 a2 = *(const float4*)(Aload2);
        float4 bv = *(const float4*)(Bload);
#pragma unroll
        for (int j = 0; j < 4; j++) {
            As[0][kseg + j][rA] = ((const float*)&a1)[j];
            As[0][kseg + j][rA + 64] = ((const float*)&a2)[j];
            Bs[0][kseg + j][rA] = ((const float*)&bv)[j];
        }
    }
    __syncthreads();

    const int nt = K >> 4;
    for (int tt = 0; tt < nt; tt++) {
        const int buf = tt & 1;
        float4 a1, a2, bv;
        if (tt + 1 < nt) {
            a1 = *(const float4*)(Aload + (tt + 1) * 16);
            a2 = *(const float4*)(Aload2 + (tt + 1) * 16);
            bv = *(const float4*)(Bload + (tt + 1) * 16);
        }
#pragma unroll
        for (int k = 0; k < 16; k++) {
            u64x2 za = *(const u64x2*)&As[buf][k][r0];
            u64x2 zb = *(const u64x2*)&As[buf][k][r0 + 4];
            u64x2 wv = *(const u64x2*)&Bs[buf][k][c0];
            u64 zp[4] = {za.x, za.y, zb.x, zb.y};
            u64 wp[2] = {wv.x, wv.y};
#pragma unroll
            for (int cp = 0; cp < 2; cp++) {
                u64 ws = swp(wp[cp]);
#pragma unroll
                for (int rp = 0; rp < 4; rp++) {
                    FFMA2(ad[rp][cp], zp[rp], wp[cp]);
                    FFMA2(ax[rp][cp], zp[rp], ws);
                }
            }
        }
        if (tt + 1 < nt) {
            const int nb = buf ^ 1;
#pragma unroll
            for (int j = 0; j < 4; j++) {
                As[nb][kseg + j][rA] = ((const float*)&a1)[j];
                As[nb][kseg + j][rA + 64] = ((const float*)&a2)[j];
                Bs[nb][kseg + j][rA] = ((const float*)&bv)[j];
            }
        }
        __syncthreads();
    }

    // epilogue: unpack diag/cross, bias + relu, float4 stores
    float b0v = bias[colBase + c0 + 0];
    float b1v = bias[colBase + c0 + 1];
    float b2v = bias[colBase + c0 + 2];
    float b3v = bias[colBase + c0 + 3];
#pragma unroll
    for (int rp = 0; rp < 4; rp++) {
        float2 d0 = unpack2(ad[rp][0]), x0 = unpack2(ax[rp][0]);
        float2 d1 = unpack2(ad[rp][1]), x1 = unpack2(ax[rp][1]);
        float4 e, o;
        e.x = fmaxf(d0.x + b0v, 0.f);
        e.y = fmaxf(x0.x + b1v, 0.f);
        e.z = fmaxf(d1.x + b2v, 0.f);
        e.w = fmaxf(x1.x + b3v, 0.f);
        o.x = fmaxf(x0.y + b0v, 0.f);
        o.y = fmaxf(d0.y + b1v, 0.f);
        o.z = fmaxf(x1.y + b2v, 0.f);
        o.w = fmaxf(d1.y + b3v, 0.f);
        *(float4*)&C[(rowBase + r0 + 2 * rp) * N + colBase + c0] = e;
        *(float4*)&C[(rowBase + r0 + 2 * rp + 1) * N + colBase + c0] = o;
    }
}

// ---------------- persistent solver -------------------------------------------
// 128 blocks x 256 threads; block b owns rows [8b, 8b+8).
// z stored NATURAL: zcol[k][r] (k = column of z, r = 0..7).
// z-update: thread = kg(8, k-split 32 each) x cg(32, 8 cols); row-pair packed
// acc (4 rp x 4 cp x {diag,cross}); w via LDG, z via LDS; 1.0 B/MAC.
__global__ __launch_bounds__(256) void solver_kernel(const float* __restrict__ b2,
                                                     const float* __restrict__ bvec,
                                                     float* __restrict__ outp) {
    extern __shared__ __align__(16) char sm[];
    float(*zcol)[8] = (float(*)[8])sm;                 // [256][8]  8192  @0
    u64(*psum)[33] = (u64(*)[33])(sm + 8192);          // [256][33] 67584 @8192
    float(*hcol)[8] = (float(*)[8])(sm + 8192);        // alias over psum
    float* Asm = (float*)(sm + 75776);                 // 131072 @75776
    float* bvs = (float*)(sm + 206848);                // 512
    u64* bps = (u64*)(sm + 207360);                    // 1024
    float* redbuf = (float*)(sm + 208384);             // 64

    const int t = threadIdx.x;
    const int r0 = blockIdx.x * 8;
    float* const zoutp = outp;
    float* const out0p = outp + 1024 * 256;

    const int kg = t >> 5;       // 0..7
    const int cg = t & 31;       // 0..31
    const int c0 = cg * 8;       // z-update cols (8)
    const int ca0 = cg * 4;      // residual cols (4)

    if (t < 128) {
        bvs[t] = bvec[t];
        bps[t] = *(const u64*)&g_biasproj[2 * t];
    }
    // stage AT into smem
    {
        const float4* src = (const float4*)g_AT;
        float4* dst = (float4*)Asm;
#pragma unroll
        for (int i = t; i < 8192; i += 256) dst[i] = src[i];
    }

    u64 ad[4][4], ax[4][4];

    // ---- phase A: out = h2 rows @ W2T + b2 (K=1024, 4 staged chunks) ----
#pragma unroll
    for (int rp = 0; rp < 4; rp++)
#pragma unroll
        for (int cp = 0; cp < 4; cp++) ad[rp][cp] = ax[rp][cp] = 0ull;

    for (int kc = 0; kc < 1024; kc += 256) {
        __syncthreads();
#pragma unroll
        for (int jj = 0; jj < 8; jj++) {
            int idx = t + 256 * jj;
            int k = idx & 255, r = idx >> 8;
            hcol[k][r] = g_h2[(r0 + r) * 1024 + kc + k];
        }
        __syncthreads();
        const float* wptr = g_W2T + (kc + kg * 32) * 256 + c0;
#pragma unroll 4
        for (int kk = 0; kk < 32; kk++) {
            int k = kg * 32 + kk;
            u64x2 za = *(const u64x2*)&hcol[k][0];
            u64x2 zb = *(const u64x2*)&hcol[k][4];
            u64x2 w0 = *(const u64x2*)(wptr);
            u64x2 w1 = *(const u64x2*)(wptr + 4);
            wptr += 256;
            u64 zp[4] = {za.x, za.y, zb.x, zb.y};
            u64 wp[4] = {w0.x, w0.y, w1.x, w1.y};
#pragma unroll
            for (int cp = 0; cp < 4; cp++) {
                u64 ws = swp(wp[cp]);
#pragma unroll
                for (int rp = 0; rp < 4; rp++) {
                    FFMA2(ad[rp][cp], zp[rp], wp[cp]);
                    FFMA2(ax[rp][cp], zp[rp], ws);
                }
            }
        }
    }
    __syncthreads();
#pragma unroll
    for (int rp = 0; rp < 4; rp++)
#pragma unroll
        for (int cp = 0; cp < 4; cp++) {
            psum[t][rp * 8 + cp * 2 + 0] = ad[rp][cp];
            psum[t][rp * 8 + cp * 2 + 1] = ax[rp][cp];
        }
    __syncthreads();
    // combine: 1024 units, bias b2, no relu, write zcol + out0p
#pragma unroll
    for (int uu = 0; uu < 4; uu++) {
        int u = t * 4 + uu;
        int cg2 = u >> 5, j = u & 31;
        int rp = j >> 3, cp = (j >> 1) & 3, dx = j & 1;
        u64 s = psum[cg2][j];
#pragma unroll
        for (int q = 1; q < 8; q++) ADD2(s, psum[q * 32 + cg2][j]);
        int c = 8 * cg2 + 2 * cp;
        u64 bb = *(const u64*)&b2[c];
        if (dx) bb = swp(bb);
        ADD2(s, bb);
        float2 v = unpack2(s);
        int cL = c + dx, cH = c + 1 - dx;
        int re = 2 * rp, ro = 2 * rp + 1;
        zcol[cL][re] = v.x;
        zcol[cH][ro] = v.y;
        out0p[(r0 + re) * 256 + cL] = v.x;
        out0p[(r0 + ro) * 256 + cH] = v.y;
    }
    __syncthreads();

    // ---- 20 fixed iterations ----
    for (int it = 0; it < 20; it++) {
        // --- z-update MAC: z @ WzT ---
#pragma unroll
        for (int rp = 0; rp < 4; rp++)
#pragma unroll
            for (int cp = 0; cp < 4; cp++) ad[rp][cp] = ax[rp][cp] = 0ull;
        {
            const float* wptr = g_WzT + (kg * 32) * 256 + c0;
#pragma unroll 4
            for (int kk = 0; kk < 32; kk++) {
                int k = kg * 32 + kk;
                u64x2 za = *(const u64x2*)&zcol[k][0];
                u64x2 zb = *(const u64x2*)&zcol[k][4];
                u64x2 w0 = *(const u64x2*)(wptr);
                u64x2 w1 = *(const u64x2*)(wptr + 4);
                wptr += 256;
                u64 zp[4] = {za.x, za.y, zb.x, zb.y};
                u64 wp[4] = {w0.x, w0.y, w1.x, w1.y};
#pragma unroll
                for (int cp = 0; cp < 4; cp++) {
                    u64 ws = swp(wp[cp]);
#pragma unroll
                    for (int rp = 0; rp < 4; rp++) {
                        FFMA2(ad[rp][cp], zp[rp], wp[cp]);
                        FFMA2(ax[rp][cp], zp[rp], ws);
                    }
                }
            }
        }
        __syncthreads();
#pragma unroll
        for (int rp = 0; rp < 4; rp++)
#pragma unroll
            for (int cp = 0; cp < 4; cp++) {
                psum[t][rp * 8 + cp * 2 + 0] = ad[rp][cp];
                psum[t][rp * 8 + cp * 2 + 1] = ax[rp][cp];
            }
        __syncthreads();
        // --- combine + bias_proj + projection, write new zcol ---
#pragma unroll
        for (int uu = 0; uu < 4; uu++) {
            int u = t * 4 + uu;
            int cg2 = u >> 5, j = u & 31;
            int rp = j >> 3, cp = (j >> 1) & 3, dx = j & 1;
            u64 s = psum[cg2][j];
#pragma unroll
            for (int q = 1; q < 8; q++) ADD2(s, psum[q * 32 + cg2][j]);
            int c = 8 * cg2 + 2 * cp;
            u64 bb = bps[(c >> 1)];
            if (dx) bb = swp(bb);
            ADD2(s, bb);
            float2 v = unpack2(s);
            if (cg2 >= 8) {  // cols >= 64 -> relu
                v.x = fmaxf(v.x, 0.f);
                v.y = fmaxf(v.y, 0.f);
            }
            zcol[c + dx][2 * rp] = v.x;
            zcol[c + 1 - dx][2 * rp + 1] = v.y;
        }
        __syncthreads();

        // --- residual MAC: z_new @ AT (A from smem, C=4) ---
        u64 rd[4][2], rx[4][2];
#pragma unroll
        for (int rp = 0; rp < 4; rp++)
#pragma unroll
            for (int cp = 0; cp < 2; cp++) rd[rp][cp] = rx[rp][cp] = 0ull;
#pragma unroll 4
        for (int kk = 0; kk < 32; kk++) {
            int k = kg * 32 + kk;
            u64x2 za = *(const u64x2*)&zcol[k][0];
            u64x2 zb = *(const u64x2*)&zcol[k][4];
            u64x2 av = *(const u64x2*)&Asm[k * 128 + ca0];
            u64 zp[4] = {za.x, za.y, zb.x, zb.y};
            u64 ap[2] = {av.x, av.y};
#pragma unroll
            for (int cp = 0; cp < 2; cp++) {
                u64 as = swp(ap[cp]);
#pragma unroll
                for (int rp = 0; rp < 4; rp++) {
                    FFMA2(rd[rp][cp], zp[rp], ap[cp]);
                    FFMA2(rx[rp][cp], zp[rp], as);
                }
            }
        }
        __syncthreads();
#pragma unroll
        for (int rp = 0; rp < 4; rp++)
#pragma unroll
            for (int cp = 0; cp < 2; cp++) {
                psum[t][rp * 4 + cp * 2 + 0] = rd[rp][cp];
                psum[t][rp * 4 + cp * 2 + 1] = rx[rp][cp];
            }
        __syncthreads();
        // --- residual combine: 512 units -> block max -> atomicMax ---
        float m = 0.f;
#pragma unroll
        for (int uu = 0; uu < 2; uu++) {
            int u = t * 2 + uu;
            int cg2 = u >> 4, j = u & 15;
            int dx = j & 1;
            int cp = (j >> 1) & 1;
            u64 s = psum[cg2][j];
#pragma unroll
            for (int q = 1; q < 8; q++) ADD2(s, psum[q * 32 + cg2][j]);
            float2 v = unpack2(s);
            int c = 4 * cg2 + 2 * cp;
            m = fmaxf(m, fmaxf(fabsf(v.x - bvs[c + dx]),
                               fabsf(v.y - bvs[c + 1 - dx])));
        }
#pragma unroll
        for (int o = 16; o; o >>= 1) m = fmaxf(m, __shfl_xor_sync(~0u, m, o));
        if ((t & 31) == 0) redbuf[t >> 5] = m;
        __syncthreads();
        if (t == 0) {
            float bm = redbuf[0];
#pragma unroll
            for (int w = 1; w < 8; w++) bm = fmaxf(bm, redbuf[w]);
            atomicMax(&g_res_arr[it], __float_as_uint(bm));
        }
        __syncthreads();
    }

    // write z_star directly to d_out
#pragma unroll
    for (int jj = 0; jj < 8; jj++) {
        int idx = t + 256 * jj;
        int c = idx & 255, r = idx >> 8;
        zoutp[(r0 + r) * 256 + c] = zcol[c][r];
    }
    __syncthreads();
    __threadfence();
    if (t == 0) {
        if (atomicAdd(&g_solver_done, 1u) == NBLK - 1) {
            int it = 21;
            for (int tt = 0; tt < 20; tt++) {
                if (__uint_as_float(g_res_arr[tt]) <= F_TOL_F) {
                    it = tt + 2;
                    break;
                }
            }
            outp[2 * 1024 * 256] = (float)it;
        }
    }
}

// ---------------- launch ------------------------------------------------------
extern "C" void kernel_launch(void* const* d_in, const int* in_sizes, int n_in,
                              void* d_out, int out_size) {
    const float* b_primal = (const float*)d_in[0];
    const float* W0 = (const float*)d_in[1];
    const float* b0 = (const float*)d_in[2];
    const float* W1 = (const float*)d_in[3];
    const float* b1 = (const float*)d_in[4];
    const float* W2 = (const float*)d_in[5];
    const float* b2 = (const float*)d_in[6];
    const float* Amat = (const float*)d_in[7];
    const float* b_vec = (const float*)d_in[8];
    const float* WzProj = (const float*)d_in[9];
    const float* WbProj = (const float*)d_in[10];

    float *h1, *h2;
    cudaGetSymbolAddress((void**)&h1, g_h1);
    cudaGetSymbolAddress((void**)&h2, g_h2);

    static int smem_set = 0;
    if (!smem_set) {
        cudaFuncSetAttribute(solver_kernel,
                             cudaFuncAttributeMaxDynamicSharedMemorySize,
                             SOLVER_SMEM);
        smem_set = 1;
    }

    prep_kernel<<<353, 1024>>>(W2, WzProj, Amat, b_vec, WbProj);

    // h1 = relu(b_primal @ W0^T + b0)   M=1024 N=1024 K=512
    gemm_relu_f2<<<dim3(16, 8), 256>>>(b_primal, W0, b0, h1, 1024, 1024, 512);
    // h2 = relu(h1 @ W1^T + b1)         M=1024 N=1024 K=1024
    gemm_relu_f2<<<dim3(16, 8), 256>>>(h1, W1, b1, h2, 1024, 1024, 1024);

    // fused: out + 20-iteration fixed-point loop, writes d_out directly
    solver_kernel<<<NBLK, 256, SOLVER_SMEM>>>(b2, b_vec, (float*)d_out);
}

// round 7
// speedup vs baseline: 1.6879x; 1.1278x over previous
#include <cuda_runtime.h>
#include <math.h>

typedef unsigned long long u64;
typedef ulonglong2 u64x2;

#define F_TOL_F 1e-6f
#define NBLK 128
#define SOLVER_SMEM 210496

// ---------------- device-global scratch (no allocations allowed) ------------
__device__ float g_h1[1024 * 1024];
__device__ float g_h2[1024 * 1024];
__device__ float g_W2T[1024 * 256];
__device__ float g_WzT[256 * 256];
__device__ float g_AT[256 * 128];
__device__ float g_biasproj[256];
__device__ unsigned g_res_arr[20];
__device__ unsigned g_solver_done;

// ---------------- packed fp32x2 (Blackwell double-rate fp32) ----------------
#define FFMA2(acc, a, b) \
    asm("fma.rn.f32x2 %0, %1, %2, %0;" : "+l"(acc) : "l"(a), "l"(b))
#define ADD2(acc, a) \
    asm("add.rn.f32x2 %0, %1, %0;" : "+l"(acc) : "l"(a))

__device__ __forceinline__ float2 unpack2(u64 v) {
    float2 p;
    asm("mov.b64 {%0,%1}, %2;" : "=f"(p.x), "=f"(p.y) : "l"(v));
    return p;
}
__device__ __forceinline__ u64 pack2(float lo, float hi) {
    u64 r;
    asm("mov.b64 %0, {%1,%2};" : "=l"(r) : "f"(lo), "f"(hi));
    return r;
}
__device__ __forceinline__ u64 swp(u64 v) {
    float2 f = unpack2(v);
    return pack2(f.y, f.x);
}

// ---------------- fused prep: 3 transposes + biasproj + state reset ---------
__global__ void prep_kernel(const float* __restrict__ W2,
                            const float* __restrict__ Wz,
                            const float* __restrict__ Am,
                            const float* __restrict__ bvec,
                            const float* __restrict__ WbP) {
    __shared__ float tb[32][33];
    const int b = blockIdx.x;
    const int t = threadIdx.x;
    const int tx = t & 31, ty = t >> 5;

    const float* in;
    float* out;
    int R, C, bx, by;
    if (b < 256) {
        in = W2; out = g_W2T; R = 256; C = 1024; bx = b & 31; by = b >> 5;
    } else if (b < 320) {
        int bb = b - 256;
        in = Wz; out = g_WzT; R = 256; C = 256; bx = bb & 7; by = bb >> 3;
    } else if (b < 352) {
        int bb = b - 320;
        in = Am; out = g_AT; R = 128; C = 256; bx = bb & 7; by = bb >> 3;
    } else {
        if (t < 20) g_res_arr[t] = 0u;
        if (t == 32) g_solver_done = 0u;
        if (t >= 256 && t < 512) {
            int j = t - 256;
            float s = 0.f;
#pragma unroll 8
            for (int i = 0; i < 128; i++) s += bvec[i] * WbP[j * 128 + i];
            g_biasproj[j] = s;
        }
        return;
    }
    int c = bx * 32 + tx, r = by * 32 + ty;
    tb[ty][tx] = in[r * C + c];
    __syncthreads();
    int oc = by * 32 + tx;
    int orr = bx * 32 + ty;
    out[orr * R + oc] = tb[tx][ty];
}

// ---------------- FFMA2 SGEMM: C = relu(A @ B^T + bias) ----------------------
// (unchanged from R6: BM=128, BN=64, BK=16, 256 thr, 8x4 tile, w-swap trick)
__global__ __launch_bounds__(256, 2) void gemm_relu_f2(
    const float* __restrict__ A, const float* __restrict__ B,
    const float* __restrict__ bias, float* __restrict__ C,
    int M, int N, int K) {
    __shared__ __align__(16) float As[2][16][128];
    __shared__ __align__(16) float Bs[2][16][64];

    const int t = threadIdx.x;
    const int tx = t & 15, ty = t >> 4;
    const int rowBase = blockIdx.y * 128;
    const int colBase = blockIdx.x * 64;
    const int c0 = 4 * tx, r0 = 8 * ty;

    const int rA = t >> 2, kseg = (t & 3) * 4;

    const float* Aload = A + (rowBase + rA) * K + kseg;
    const float* Aload2 = A + (rowBase + rA + 64) * K + kseg;
    const float* Bload = B + (colBase + rA) * K + kseg;

    u64 ad[4][2], ax[4][2];
#pragma unroll
    for (int rp = 0; rp < 4; rp++)
#pragma unroll
        for (int cp = 0; cp < 2; cp++) ad[rp][cp] = ax[rp][cp] = 0ull;

    {
        float4 a1 = *(const float4*)(Aload);
        float4 a2 = *(const float4*)(Aload2);
        float4 bv = *(const float4*)(Bload);
#pragma unroll
        for (int j = 0; j < 4; j++) {
            As[0][kseg + j][rA] = ((const float*)&a1)[j];
            As[0][kseg + j][rA + 64] = ((const float*)&a2)[j];
            Bs[0][kseg + j][rA] = ((const float*)&bv)[j];
        }
    }
    __syncthreads();

    const int nt = K >> 4;
    for (int tt = 0; tt < nt; tt++) {
        const int buf = tt & 1;
        float4 a1, a2, bv;
        if (tt + 1 < nt) {
            a1 = *(const float4*)(Aload + (tt + 1) * 16);
            a2 = *(const float4*)(Aload2 + (tt + 1) * 16);
            bv = *(const float4*)(Bload + (tt + 1) * 16);
        }
#pragma unroll
        for (int k = 0; k < 16; k++) {
            u64x2 za = *(const u64x2*)&As[buf][k][r0];
            u64x2 zb = *(const u64x2*)&As[buf][k][r0 + 4];
            u64x2 wv = *(const u64x2*)&Bs[buf][k][c0];
            u64 zp[4] = {za.x, za.y, zb.x, zb.y};
            u64 wp[2] = {wv.x, wv.y};
#pragma unroll
            for (int cp = 0; cp < 2; cp++) {
                u64 ws = swp(wp[cp]);
#pragma unroll
                for (int rp = 0; rp < 4; rp++) {
                    FFMA2(ad[rp][cp], zp[rp], wp[cp]);
                    FFMA2(ax[rp][cp], zp[rp], ws);
                }
            }
        }
        if (tt + 1 < nt) {
            const int nb = buf ^ 1;
#pragma unroll
            for (int j = 0; j < 4; j++) {
                As[nb][kseg + j][rA] = ((const float*)&a1)[j];
                As[nb][kseg + j][rA + 64] = ((const float*)&a2)[j];
                Bs[nb][kseg + j][rA] = ((const float*)&bv)[j];
            }
        }
        __syncthreads();
    }

    float b0v = bias[colBase + c0 + 0];
    float b1v = bias[colBase + c0 + 1];
    float b2v = bias[colBase + c0 + 2];
    float b3v = bias[colBase + c0 + 3];
#pragma unroll
    for (int rp = 0; rp < 4; rp++) {
        float2 d0 = unpack2(ad[rp][0]), x0 = unpack2(ax[rp][0]);
        float2 d1 = unpack2(ad[rp][1]), x1 = unpack2(ax[rp][1]);
        float4 e, o;
        e.x = fmaxf(d0.x + b0v, 0.f);
        e.y = fmaxf(x0.x + b1v, 0.f);
        e.z = fmaxf(d1.x + b2v, 0.f);
        e.w = fmaxf(x1.x + b3v, 0.f);
        o.x = fmaxf(x0.y + b0v, 0.f);
        o.y = fmaxf(d0.y + b1v, 0.f);
        o.z = fmaxf(x1.y + b2v, 0.f);
        o.w = fmaxf(d1.y + b3v, 0.f);
        *(float4*)&C[(rowBase + r0 + 2 * rp) * N + colBase + c0] = e;
        *(float4*)&C[(rowBase + r0 + 2 * rp + 1) * N + colBase + c0] = o;
    }
}

// ---------------- persistent solver: 512 threads (16 warps/SM) ---------------
// 128 blocks; block b owns rows [8b, 8b+8). z natural layout zcol[k][r].
// z-update: kg = t>>6 (8 x 32k), cg = t&63 (4 cols). Residual: kgr = t>>5
// (16 x 16k), ag = t&31 (4 cols). Row-pair packed accs + w-swap trick.
__global__ __launch_bounds__(512) void solver_kernel(const float* __restrict__ b2,
                                                     const float* __restrict__ bvec,
                                                     float* __restrict__ outp) {
    extern __shared__ __align__(16) char sm[];
    float(*zcol)[8] = (float(*)[8])sm;            // [256][8]   8192 @0
    u64(*psum)[17] = (u64(*)[17])(sm + 8192);     // [512][17] 69632 @8192
    float(*hcol)[8] = (float(*)[8])(sm + 8192);   // alias over psum
    float* Asm = (float*)(sm + 77824);            // 131072 @77824
    float* bvs = (float*)(sm + 208896);           // 512
    u64* bps = (u64*)(sm + 209408);               // 1024
    float* redbuf = (float*)(sm + 210432);        // 64

    const int t = threadIdx.x;
    const int r0 = blockIdx.x * 8;
    float* const zoutp = outp;
    float* const out0p = outp + 1024 * 256;

    const int kg = t >> 6;   // 0..7
    const int cg = t & 63;   // 0..63
    const int c0 = cg * 4;
    const int kgr = t >> 5;  // 0..15
    const int ag = t & 31;   // 0..31
    const int ca0 = ag * 4;

    if (t < 128) {
        bvs[t] = bvec[t];
        bps[t] = *(const u64*)&g_biasproj[2 * t];
    }
    // stage AT into smem
    {
        const float4* src = (const float4*)g_AT;
        float4* dst = (float4*)Asm;
#pragma unroll
        for (int i = t; i < 8192; i += 512) dst[i] = src[i];
    }

    u64 ad[4][2], ax[4][2];

    // ---- phase A: out = h2 rows @ W2T + b2 (K=1024, 4 chunks) ----
#pragma unroll
    for (int rp = 0; rp < 4; rp++)
#pragma unroll
        for (int cp = 0; cp < 2; cp++) ad[rp][cp] = ax[rp][cp] = 0ull;

    for (int kc = 0; kc < 1024; kc += 256) {
        __syncthreads();
#pragma unroll
        for (int jj = 0; jj < 4; jj++) {
            int idx = t + 512 * jj;
            int k = idx & 255, r = idx >> 8;
            hcol[k][r] = g_h2[(r0 + r) * 1024 + kc + k];
        }
        __syncthreads();
        const float* wptr = g_W2T + (kc + kg * 32) * 256 + c0;
#pragma unroll 4
        for (int kk = 0; kk < 32; kk++) {
            int k = kg * 32 + kk;
            u64x2 za = *(const u64x2*)&hcol[k][0];
            u64x2 zb = *(const u64x2*)&hcol[k][4];
            u64x2 wv = *(const u64x2*)(wptr);
            wptr += 256;
            u64 zp[4] = {za.x, za.y, zb.x, zb.y};
            u64 wp[2] = {wv.x, wv.y};
#pragma unroll
            for (int cp = 0; cp < 2; cp++) {
                u64 ws = swp(wp[cp]);
#pragma unroll
                for (int rp = 0; rp < 4; rp++) {
                    FFMA2(ad[rp][cp], zp[rp], wp[cp]);
                    FFMA2(ax[rp][cp], zp[rp], ws);
                }
            }
        }
    }
    __syncthreads();
#pragma unroll
    for (int rp = 0; rp < 4; rp++)
#pragma unroll
        for (int cp = 0; cp < 2; cp++) {
            psum[t][rp * 4 + cp * 2 + 0] = ad[rp][cp];
            psum[t][rp * 4 + cp * 2 + 1] = ax[rp][cp];
        }
    __syncthreads();
    // combine (1024 units, 2/thread): + b2, no relu, write zcol + out
#pragma unroll
    for (int uu = 0; uu < 2; uu++) {
        int u = t * 2 + uu;
        int cg2 = u >> 4, j = u & 15;
        int rp = j >> 2, cp = (j >> 1) & 1, dx = j & 1;
        u64 s = psum[cg2][j];
#pragma unroll
        for (int q = 1; q < 8; q++) ADD2(s, psum[q * 64 + cg2][j]);
        int c = 4 * cg2 + 2 * cp;
        u64 bb = *(const u64*)&b2[c];
        if (dx) bb = swp(bb);
        ADD2(s, bb);
        float2 v = unpack2(s);
        int cL = c + dx, cH = c + 1 - dx;
        int re = 2 * rp, ro = 2 * rp + 1;
        zcol[cL][re] = v.x;
        zcol[cH][ro] = v.y;
        out0p[(r0 + re) * 256 + cL] = v.x;
        out0p[(r0 + ro) * 256 + cH] = v.y;
    }
    __syncthreads();

    // ---- 20 fixed iterations ----
    for (int it = 0; it < 20; it++) {
        // --- z-update MAC: z @ WzT ---
#pragma unroll
        for (int rp = 0; rp < 4; rp++)
#pragma unroll
            for (int cp = 0; cp < 2; cp++) ad[rp][cp] = ax[rp][cp] = 0ull;
        {
            const float* wptr = g_WzT + (kg * 32) * 256 + c0;
#pragma unroll 4
            for (int kk = 0; kk < 32; kk++) {
                int k = kg * 32 + kk;
                u64x2 za = *(const u64x2*)&zcol[k][0];
                u64x2 zb = *(const u64x2*)&zcol[k][4];
                u64x2 wv = *(const u64x2*)(wptr);
                wptr += 256;
                u64 zp[4] = {za.x, za.y, zb.x, zb.y};
                u64 wp[2] = {wv.x, wv.y};
#pragma unroll
                for (int cp = 0; cp < 2; cp++) {
                    u64 ws = swp(wp[cp]);
#pragma unroll
                    for (int rp = 0; rp < 4; rp++) {
                        FFMA2(ad[rp][cp], zp[rp], wp[cp]);
                        FFMA2(ax[rp][cp], zp[rp], ws);
                    }
                }
            }
        }
        __syncthreads();
#pragma unroll
        for (int rp = 0; rp < 4; rp++)
#pragma unroll
            for (int cp = 0; cp < 2; cp++) {
                psum[t][rp * 4 + cp * 2 + 0] = ad[rp][cp];
                psum[t][rp * 4 + cp * 2 + 1] = ax[rp][cp];
            }
        __syncthreads();
        // --- combine + bias_proj + projection, write new zcol ---
#pragma unroll
        for (int uu = 0; uu < 2; uu++) {
            int u = t * 2 + uu;
            int cg2 = u >> 4, j = u & 15;
            int rp = j >> 2, cp = (j >> 1) & 1, dx = j & 1;
            u64 s = psum[cg2][j];
#pragma unroll
            for (int q = 1; q < 8; q++) ADD2(s, psum[q * 64 + cg2][j]);
            int c = 4 * cg2 + 2 * cp;
            u64 bb = bps[2 * cg2 + cp];
            if (dx) bb = swp(bb);
            ADD2(s, bb);
            float2 v = unpack2(s);
            if (cg2 >= 16) {  // cols >= 64 -> relu
                v.x = fmaxf(v.x, 0.f);
                v.y = fmaxf(v.y, 0.f);
            }
            zcol[c + dx][2 * rp] = v.x;
            zcol[c + 1 - dx][2 * rp + 1] = v.y;
        }
        __syncthreads();

        // --- residual MAC: z_new @ AT (A from smem) ---
        u64 rd[4][2], rx[4][2];
#pragma unroll
        for (int rp = 0; rp < 4; rp++)
#pragma unroll
            for (int cp = 0; cp < 2; cp++) rd[rp][cp] = rx[rp][cp] = 0ull;
#pragma unroll 4
        for (int kk = 0; kk < 16; kk++) {
            int k = kgr * 16 + kk;
            u64x2 za = *(const u64x2*)&zcol[k][0];
            u64x2 zb = *(const u64x2*)&zcol[k][4];
            u64x2 av = *(const u64x2*)&Asm[k * 128 + ca0];
            u64 zp[4] = {za.x, za.y, zb.x, zb.y};
            u64 ap[2] = {av.x, av.y};
#pragma unroll
            for (int cp = 0; cp < 2; cp++) {
                u64 as = swp(ap[cp]);
#pragma unroll
                for (int rp = 0; rp < 4; rp++) {
                    FFMA2(rd[rp][cp], zp[rp], ap[cp]);
                    FFMA2(rx[rp][cp], zp[rp], as);
                }
            }
        }
        __syncthreads();
#pragma unroll
        for (int rp = 0; rp < 4; rp++)
#pragma unroll
            for (int cp = 0; cp < 2; cp++) {
                psum[t][rp * 4 + cp * 2 + 0] = rd[rp][cp];
                psum[t][rp * 4 + cp * 2 + 1] = rx[rp][cp];
            }
        __syncthreads();
        // --- residual combine: 512 units, 1/thread ---
        float m = 0.f;
        {
            int u = t;
            int ag2 = u >> 4, j = u & 15;
            int cp = (j >> 1) & 1, dx = j & 1;
            u64 s = psum[ag2][j];
#pragma unroll
            for (int q = 1; q < 16; q++) ADD2(s, psum[q * 32 + ag2][j]);
            float2 v = unpack2(s);
            int c = 4 * ag2 + 2 * cp;
            m = fmaxf(fabsf(v.x - bvs[c + dx]), fabsf(v.y - bvs[c + 1 - dx]));
        }
#pragma unroll
        for (int o = 16; o; o >>= 1) m = fmaxf(m, __shfl_xor_sync(~0u, m, o));
        if ((t & 31) == 0) redbuf[t >> 5] = m;
        __syncthreads();
        if (t == 0) {
            float bm = redbuf[0];
#pragma unroll
            for (int w = 1; w < 16; w++) bm = fmaxf(bm, redbuf[w]);
            atomicMax(&g_res_arr[it], __float_as_uint(bm));
        }
        __syncthreads();
    }

    // write z_star directly to d_out
#pragma unroll
    for (int jj = 0; jj < 4; jj++) {
        int idx = t + 512 * jj;
        int c = idx & 255, r = idx >> 8;
        zoutp[(r0 + r) * 256 + c] = zcol[c][r];
    }
    __syncthreads();
    __threadfence();
    if (t == 0) {
        if (atomicAdd(&g_solver_done, 1u) == NBLK - 1) {
            int it = 21;
            for (int tt = 0; tt < 20; tt++) {
                if (__uint_as_float(g_res_arr[tt]) <= F_TOL_F) {
                    it = tt + 2;
                    break;
                }
            }
            outp[2 * 1024 * 256] = (float)it;
        }
    }
}

// ---------------- launch ------------------------------------------------------
extern "C" void kernel_launch(void* const* d_in, const int* in_sizes, int n_in,
                              void* d_out, int out_size) {
    const float* b_primal = (const float*)d_in[0];
    const float* W0 = (const float*)d_in[1];
    const float* b0 = (const float*)d_in[2];
    const float* W1 = (const float*)d_in[3];
    const float* b1 = (const float*)d_in[4];
    const float* W2 = (const float*)d_in[5];
    const float* b2 = (const float*)d_in[6];
    const float* Amat = (const float*)d_in[7];
    const float* b_vec = (const float*)d_in[8];
    const float* WzProj = (const float*)d_in[9];
    const float* WbProj = (const float*)d_in[10];

    float *h1, *h2;
    cudaGetSymbolAddress((void**)&h1, g_h1);
    cudaGetSymbolAddress((void**)&h2, g_h2);

    static int smem_set = 0;
    if (!smem_set) {
        cudaFuncSetAttribute(solver_kernel,
                             cudaFuncAttributeMaxDynamicSharedMemorySize,
                             SOLVER_SMEM);
        smem_set = 1;
    }

    prep_kernel<<<353, 1024>>>(W2, WzProj, Amat, b_vec, WbProj);

    // h1 = relu(b_primal @ W0^T + b0)   M=1024 N=1024 K=512
    gemm_relu_f2<<<dim3(16, 8), 256>>>(b_primal, W0, b0, h1, 1024, 1024, 512);
    // h2 = relu(h1 @ W1^T + b1)         M=1024 N=1024 K=1024
    gemm_relu_f2<<<dim3(16, 8), 256>>>(h1, W1, b1, h2, 1024, 1024, 1024);

    // fused: out + 20-iteration fixed-point loop, writes d_out directly
    solver_kernel<<<NBLK, 512, SOLVER_SMEM>>>(b2, b_vec, (float*)d_out);
}